// round 3
// baseline (speedup 1.0000x reference)
#include <cuda_runtime.h>
#include <math.h>

// Problem constants
#define N_SAMPLES 32768
#define N_FRAMES  128
#define STEP      (N_SAMPLES / N_FRAMES)   // 256
#define N_FREQS   16
#define POS_DIM   (2 * N_FREQS + 1)        // 33
#define MODEL_DIM 128
#define N_ROWS    512                      // B * N_EVENTS = 32 * 16

#ifndef M_PI
#define M_PI 3.14159265358979323846
#endif

// Scratch (no cudaMalloc allowed): normalized pos encoding + per-row delay
__device__ float g_posn[N_FRAMES * POS_DIM];
__device__ int   g_delay[N_ROWS];

// ---------------------------------------------------------------------------
// Kernel 0: compute the normalized positional-encoding table (128 x 33).
// Trig done in double on the exact f32 argument to match numpy's f32 sin/cos
// to <=1 ulp (protects argmax from spurious flips). One block, 128 threads.
// ---------------------------------------------------------------------------
__global__ void pos_kernel() {
    int f = threadIdx.x;  // 0..127
    // np.linspace(-pi, pi, 128): computed in double, cast to f32
    double xd = -M_PI + (double)f * (2.0 * M_PI / 127.0);
    float x = (float)xd;

    float feat[POS_DIM];
    feat[0] = x;
#pragma unroll
    for (int i = 0; i < N_FREQS; i++) {
        float a = ldexpf(x, i);               // 2^i * x, exact in f32
        feat[1 + 2 * i] = (float)sin((double)a);
        feat[2 + 2 * i] = (float)cos((double)a);
    }
    float nrm = 0.0f;
#pragma unroll
    for (int j = 0; j < POS_DIM; j++) nrm += feat[j] * feat[j];
    float inv = 1.0f / (sqrtf(nrm) + 1e-8f);
#pragma unroll
    for (int j = 0; j < POS_DIM; j++) g_posn[f * POS_DIM + j] = feat[j] * inv;
}

// ---------------------------------------------------------------------------
// Kernel 1: per row, p = time_latent @ W + b (33 values), then
// sim_f = p . posn_f for f in 0..127, block argmax -> delay = 256 * argmax.
// (p's own normalization is a positive scalar per row: argmax-invariant.)
// One block per row, 128 threads.
// ---------------------------------------------------------------------------
__global__ void argmax_kernel(const float* __restrict__ tl,
                              const float* __restrict__ W,
                              const float* __restrict__ b) {
    int row = blockIdx.x;
    int tid = threadIdx.x;

    __shared__ float s_tl[MODEL_DIM];
    __shared__ float s_p[POS_DIM];
    __shared__ float s_val[128];
    __shared__ int   s_idx[128];

    s_tl[tid] = tl[row * MODEL_DIM + tid];
    __syncthreads();

    if (tid < POS_DIM) {
        float acc = 0.0f;
#pragma unroll 8
        for (int k = 0; k < MODEL_DIM; k++)
            acc += s_tl[k] * W[k * POS_DIM + tid];  // W is (128, 33) row-major
        s_p[tid] = acc + b[tid];
    }
    __syncthreads();

    // thread tid handles frame f = tid
    float dot = 0.0f;
#pragma unroll
    for (int j = 0; j < POS_DIM; j++)
        dot += s_p[j] * g_posn[tid * POS_DIM + j];

    s_val[tid] = dot;
    s_idx[tid] = tid;
    __syncthreads();

    // argmax reduction; on exact tie prefer the lower index (first occurrence,
    // matching jnp.argmax)
    for (int s = 64; s > 0; s >>= 1) {
        if (tid < s) {
            float vu = s_val[tid + s];
            int   iu = s_idx[tid + s];
            if (vu > s_val[tid] || (vu == s_val[tid] && iu < s_idx[tid])) {
                s_val[tid] = vu;
                s_idx[tid] = iu;
            }
        }
        __syncthreads();
    }
    if (tid == 0) g_delay[row] = s_idx[0] * STEP;
}

// ---------------------------------------------------------------------------
// Kernel 2: the actual output. Delta convolution == shift:
//   out[row, t] = (t >= d) ? stems[row, t - d] * (1/256) : 0
// d is a multiple of 256 -> float4 accesses stay 16B-aligned on both sides.
// grid: (32768 / (256*4), 512) = (32, 512), 256 threads.
// ---------------------------------------------------------------------------
__global__ void shift_kernel(const float* __restrict__ stems,
                             float* __restrict__ out) {
    int row = blockIdx.y;
    int t = (blockIdx.x * blockDim.x + threadIdx.x) * 4;
    int d = g_delay[row];

    const float SCALE = 1.0f / 256.0f;  // 1/sqrt(2*N_SAMPLES), exact power of two

    float4 v;
    if (t >= d) {
        const float4* src =
            reinterpret_cast<const float4*>(stems + (size_t)row * N_SAMPLES + (t - d));
        float4 s = *src;
        v.x = s.x * SCALE; v.y = s.y * SCALE; v.z = s.z * SCALE; v.w = s.w * SCALE;
    } else {
        v.x = v.y = v.z = v.w = 0.0f;
    }
    reinterpret_cast<float4*>(out + (size_t)row * N_SAMPLES)[t >> 2] = v;
}

// ---------------------------------------------------------------------------
extern "C" void kernel_launch(void* const* d_in, const int* in_sizes, int n_in,
                              void* d_out, int out_size) {
    // metadata order: time_latent, stems, targets (unused), W, b
    const float* tl    = (const float*)d_in[0];
    const float* stems = (const float*)d_in[1];
    const float* W     = (const float*)d_in[3];
    const float* b     = (const float*)d_in[4];
    float* out = (float*)d_out;

    pos_kernel<<<1, N_FRAMES>>>();
    argmax_kernel<<<N_ROWS, 128>>>(tl, W, b);

    dim3 grid(N_SAMPLES / (256 * 4), N_ROWS);
    shift_kernel<<<grid, 256>>>(stems, out);
}

// round 6
// speedup vs baseline: 1.5122x; 1.5122x over previous
#include <cuda_runtime.h>
#include <math.h>

// Problem constants
#define N_SAMPLES 32768
#define N_FRAMES  128
#define STEP      (N_SAMPLES / N_FRAMES)   // 256
#define N_FREQS   16
#define POS_DIM   (2 * N_FREQS + 1)        // 33
#define MODEL_DIM 128
#define N_ROWS    512                      // B * N_EVENTS = 32 * 16

#ifndef M_PI
#define M_PI 3.14159265358979323846
#endif

// Scratch (no cudaMalloc allowed): normalized pos encoding + per-row delay
__device__ float g_posn[N_FRAMES * POS_DIM];
__device__ int   g_delay[N_ROWS];

// ---------------------------------------------------------------------------
// Kernel 0: normalized positional-encoding table (128 x 33).
//
// Instead of 32 double sin/cos calls per thread with huge arguments (2^15*pi
// triggers Payne-Hanek slow-path range reduction — this was 32.7us), compute
// sin(x), cos(x) once for |x| <= pi (fast polynomial path) and derive all
// sin/cos(2^i x) by the double-angle recurrence in double precision:
//     s' = 2 s c,  c' = 1 - 2 s^2
// Error amplification ~2x per step: 2^16 * 1e-16 ~ 7e-12 absolute — four
// orders of magnitude below f32 ulp, so the f32-cast table is bit-identical
// (w.r.t. argmax behavior) to the full double-trig version that passed.
// Note 2^i * x is exact in f32 (power-of-two scaling), so the recurrence
// target angle equals the reference's f32 argument exactly.
// ---------------------------------------------------------------------------
__global__ void pos_kernel() {
    int f = threadIdx.x;  // 0..127, one thread per frame
    // np.linspace(-pi, pi, 128): computed in double, cast to f32
    double xd = -M_PI + (double)f * (2.0 * M_PI / 127.0);
    float x = (float)xd;

    double s = sin((double)x);   // |x| <= pi: fast path
    double c = cos((double)x);

    float feat[POS_DIM];
    feat[0] = x;
#pragma unroll
    for (int i = 0; i < N_FREQS; i++) {
        feat[1 + 2 * i] = (float)s;   // sin(2^i * x)
        feat[2 + 2 * i] = (float)c;   // cos(2^i * x)
        double s2 = 2.0 * s * c;
        double c2 = fma(-2.0 * s, s, 1.0);   // 1 - 2 s^2
        s = s2;
        c = c2;
    }

    float nrm = 0.0f;
#pragma unroll
    for (int j = 0; j < POS_DIM; j++) nrm += feat[j] * feat[j];
    float inv = 1.0f / (sqrtf(nrm) + 1e-8f);
#pragma unroll
    for (int j = 0; j < POS_DIM; j++) g_posn[f * POS_DIM + j] = feat[j] * inv;
}

// ---------------------------------------------------------------------------
// Kernel 1: per row, p = time_latent @ W + b (33 values), then
// sim_f = p . posn_f for f in 0..127, block argmax -> delay = 256 * argmax.
// (p's own normalization is a positive scalar per row: argmax-invariant.)
// One block per row, 128 threads.
// ---------------------------------------------------------------------------
__global__ void argmax_kernel(const float* __restrict__ tl,
                              const float* __restrict__ W,
                              const float* __restrict__ b) {
    int row = blockIdx.x;
    int tid = threadIdx.x;

    __shared__ float s_tl[MODEL_DIM];
    __shared__ float s_p[POS_DIM];
    __shared__ float s_val[128];
    __shared__ int   s_idx[128];

    s_tl[tid] = tl[row * MODEL_DIM + tid];
    __syncthreads();

    if (tid < POS_DIM) {
        float acc = 0.0f;
#pragma unroll 8
        for (int k = 0; k < MODEL_DIM; k++)
            acc += s_tl[k] * W[k * POS_DIM + tid];  // W is (128, 33) row-major
        s_p[tid] = acc + b[tid];
    }
    __syncthreads();

    // thread tid handles frame f = tid
    float dot = 0.0f;
#pragma unroll
    for (int j = 0; j < POS_DIM; j++)
        dot += s_p[j] * g_posn[tid * POS_DIM + j];

    s_val[tid] = dot;
    s_idx[tid] = tid;
    __syncthreads();

    // argmax reduction; on exact tie prefer the lower index (first occurrence,
    // matching jnp.argmax)
    for (int s = 64; s > 0; s >>= 1) {
        if (tid < s) {
            float vu = s_val[tid + s];
            int   iu = s_idx[tid + s];
            if (vu > s_val[tid] || (vu == s_val[tid] && iu < s_idx[tid])) {
                s_val[tid] = vu;
                s_idx[tid] = iu;
            }
        }
        __syncthreads();
    }
    if (tid == 0) g_delay[row] = s_idx[0] * STEP;
}

// ---------------------------------------------------------------------------
// Kernel 2: the actual output. Delta convolution == shift:
//   out[row, t] = (t >= d) ? stems[row, t - d] * (1/256) : 0
// d is a multiple of 256 -> float4 accesses stay 16B-aligned on both sides.
// grid: (32768 / (256*4), 512) = (32, 512), 256 threads. DRAM-bound: 128MB.
// ---------------------------------------------------------------------------
__global__ void shift_kernel(const float* __restrict__ stems,
                             float* __restrict__ out) {
    int row = blockIdx.y;
    int t = (blockIdx.x * blockDim.x + threadIdx.x) * 4;
    int d = g_delay[row];

    const float SCALE = 1.0f / 256.0f;  // 1/sqrt(2*N_SAMPLES), exact power of two

    float4 v;
    if (t >= d) {
        const float4* src =
            reinterpret_cast<const float4*>(stems + (size_t)row * N_SAMPLES + (t - d));
        float4 s = *src;
        v.x = s.x * SCALE; v.y = s.y * SCALE; v.z = s.z * SCALE; v.w = s.w * SCALE;
    } else {
        v.x = v.y = v.z = v.w = 0.0f;
    }
    reinterpret_cast<float4*>(out + (size_t)row * N_SAMPLES)[t >> 2] = v;
}

// ---------------------------------------------------------------------------
extern "C" void kernel_launch(void* const* d_in, const int* in_sizes, int n_in,
                              void* d_out, int out_size) {
    // metadata order: time_latent, stems, targets (unused), W, b
    const float* tl    = (const float*)d_in[0];
    const float* stems = (const float*)d_in[1];
    const float* W     = (const float*)d_in[3];
    const float* b     = (const float*)d_in[4];
    float* out = (float*)d_out;

    pos_kernel<<<1, N_FRAMES>>>();
    argmax_kernel<<<N_ROWS, 128>>>(tl, W, b);

    dim3 grid(N_SAMPLES / (256 * 4), N_ROWS);
    shift_kernel<<<grid, 256>>>(stems, out);
}

// round 7
// speedup vs baseline: 2.1889x; 1.4475x over previous
#include <cuda_runtime.h>
#include <math.h>

// Problem constants
#define N_SAMPLES 32768
#define N_FRAMES  128
#define STEP      (N_SAMPLES / N_FRAMES)   // 256
#define N_FREQS   16
#define POS_DIM   (2 * N_FREQS + 1)        // 33
#define MODEL_DIM 128
#define N_ROWS    512                      // B * N_EVENTS = 32 * 16

#define PI_D 3.14159265358979323846

// ---------------------------------------------------------------------------
// COMPILE-TIME positional-encoding table.
// The table depends on no runtime input, so the whole thing (f32 linspace,
// sin/cos(2^i x) via double-angle recurrence in double, f32 normalization)
// is evaluated by constexpr at compile time. This removes the 10.9us
// pos_kernel from the device timeline entirely.
//
// Accuracy: Taylor for |x|<=pi gives core sin/cos to ~4e-15 abs; the 16
// double-angle steps amplify by ~2^16 -> ~3e-10 abs — 200x below half an
// f32 ulp, so the f32 table (and every argmax) matches the previously
// passing library-trig version.
// ---------------------------------------------------------------------------
struct PosTable { float v[N_FRAMES * POS_DIM]; };

constexpr double csin_core(double x) {            // |x| <= pi
    double x2 = x * x, term = x, sum = x;
    for (int k = 1; k <= 25; k++) {
        term *= -x2 / (double)((2 * k) * (2 * k + 1));
        sum += term;
    }
    return sum;
}
constexpr double ccos_core(double x) {            // |x| <= pi
    double x2 = x * x, term = 1.0, sum = 1.0;
    for (int k = 1; k <= 25; k++) {
        term *= -x2 / (double)((2 * k - 1) * (2 * k));
        sum += term;
    }
    return sum;
}
constexpr double csqrt_d(double x) {              // Newton, x > 0
    double g = x > 1.0 ? x : 1.0;
    for (int i = 0; i < 80; i++) g = 0.5 * (g + x / g);
    return g;
}

constexpr PosTable make_pos_table() {
    PosTable T{};
    for (int f = 0; f < N_FRAMES; f++) {
        // np.linspace(-pi, pi, 128) in double, cast to f32
        double xd = -PI_D + (double)f * (2.0 * PI_D / 127.0);
        float x = (float)xd;

        double s = csin_core((double)x);
        double c = ccos_core((double)x);

        float feat[POS_DIM] = {};
        feat[0] = x;
        for (int i = 0; i < N_FREQS; i++) {
            feat[1 + 2 * i] = (float)s;           // sin(2^i * x)
            feat[2 + 2 * i] = (float)c;           // cos(2^i * x)
            double s2 = 2.0 * s * c;
            double c2 = 1.0 - 2.0 * s * s;
            s = s2; c = c2;
        }
        float nrm = 0.0f;
        for (int j = 0; j < POS_DIM; j++) nrm += feat[j] * feat[j];
        float inv = 1.0f / ((float)csqrt_d((double)nrm) + 1e-8f);
        for (int j = 0; j < POS_DIM; j++) T.v[f * POS_DIM + j] = feat[j] * inv;
    }
    return T;
}

constexpr PosTable kPosTable = make_pos_table();   // evaluated at compile time
__device__ const PosTable g_pos = kPosTable;       // static (constant) init

// ---------------------------------------------------------------------------
// ONE fused kernel, one block per row (512 blocks x 256 threads):
//   1. p = time_latent[row] @ W + b        (33 outputs; GEMV in shared)
//   2. sim_f = p . posn_f, f = 0..127      (p's norm is a positive scalar:
//                                           argmax-invariant, so skipped)
//   3. block argmax -> delay d = 256 * argmax (ties -> lowest index)
//   4. delta convolution == shift:
//        out[row,t] = (t >= d) ? stems[row, t-d] / 256 : 0
//      d is a multiple of 256 -> float4 stays 16B-aligned on both sides.
// Streaming phase moves 128MB total: DRAM-bound (~20us floor).
// ---------------------------------------------------------------------------
__global__ void __launch_bounds__(256) fused_kernel(
        const float* __restrict__ tl,
        const float* __restrict__ W,
        const float* __restrict__ b,
        const float* __restrict__ stems,
        float* __restrict__ out) {
    int row = blockIdx.x;
    int tid = threadIdx.x;   // 0..255

    __shared__ float s_tl[MODEL_DIM];
    __shared__ float s_p[POS_DIM];
    __shared__ float s_val[N_FRAMES];
    __shared__ int   s_idx[N_FRAMES];
    __shared__ int   s_delay;

    if (tid < MODEL_DIM) s_tl[tid] = tl[row * MODEL_DIM + tid];
    __syncthreads();

    if (tid < POS_DIM) {
        float acc = 0.0f;
#pragma unroll 8
        for (int k = 0; k < MODEL_DIM; k++)
            acc += s_tl[k] * W[k * POS_DIM + tid];   // W is (128, 33) row-major
        s_p[tid] = acc + b[tid];
    }
    __syncthreads();

    if (tid < N_FRAMES) {
        float dot = 0.0f;
#pragma unroll
        for (int j = 0; j < POS_DIM; j++)
            dot += s_p[j] * g_pos.v[tid * POS_DIM + j];
        s_val[tid] = dot;
        s_idx[tid] = tid;
    }
    __syncthreads();

    // argmax reduction over 128 frames; exact tie -> lower index (jnp.argmax)
    for (int s = 64; s > 0; s >>= 1) {
        if (tid < s) {
            float vu = s_val[tid + s];
            int   iu = s_idx[tid + s];
            if (vu > s_val[tid] || (vu == s_val[tid] && iu < s_idx[tid])) {
                s_val[tid] = vu;
                s_idx[tid] = iu;
            }
        }
        __syncthreads();
    }
    if (tid == 0) s_delay = s_idx[0] * STEP;
    __syncthreads();

    const int d = s_delay;
    const float SCALE = 1.0f / 256.0f;   // 1/sqrt(2*N_SAMPLES), exact pow2

    const float* src = stems + (size_t)row * N_SAMPLES;
    float4* dst = reinterpret_cast<float4*>(out + (size_t)row * N_SAMPLES);

    // 32768 samples / (256 threads * 4) = 32 iterations
#pragma unroll 8
    for (int it = 0; it < N_SAMPLES / (256 * 4); it++) {
        int t = (it * 256 + tid) * 4;
        float4 v;
        if (t >= d) {
            float4 s4 = *reinterpret_cast<const float4*>(src + (t - d));
            v.x = s4.x * SCALE; v.y = s4.y * SCALE;
            v.z = s4.z * SCALE; v.w = s4.w * SCALE;
        } else {
            v.x = v.y = v.z = v.w = 0.0f;
        }
        dst[t >> 2] = v;
    }
}

// ---------------------------------------------------------------------------
extern "C" void kernel_launch(void* const* d_in, const int* in_sizes, int n_in,
                              void* d_out, int out_size) {
    // metadata order: time_latent, stems, targets (unused), W, b
    const float* tl    = (const float*)d_in[0];
    const float* stems = (const float*)d_in[1];
    const float* W     = (const float*)d_in[3];
    const float* b     = (const float*)d_in[4];
    float* out = (float*)d_out;

    fused_kernel<<<N_ROWS, 256>>>(tl, W, b, stems, out);
}